// round 9
// baseline (speedup 1.0000x reference)
#include <cuda_runtime.h>
#include <cuda_bf16.h>

// ConvTreeBlock: N=1e6 nodes, C=16, KS=9.
// R9 = R8 resubmitted verbatim (R8 bench was an infra failure, no data).
// R8: 4 lanes per node gather (1 LDG.128 per node-row => minimum L1tex
// wavefronts: 8 lines per warp-gather, halved vs R5) + butterfly shfl exchange
// (xor1 then xor2, static-indexed SELs) + f32x2 FMA. Fused stats + BN1-in-gather.
// Launches: zero_stats -> conv1(+stats1) -> conv2(BN1+leaky inline, +stats2) -> bnact2.

#define NMAX 1000000

__device__ float g_y1[(size_t)NMAX * 16];   // conv1 raw output (device-side only!)
__device__ float g_stats[64];               // [0:16]sum1 [16:32]ssq1 [32:48]sum2 [48:64]ssq2

static constexpr float EPS   = 1e-5f;
static constexpr float SLOPE = 0.2f;

// ---- f32x2 helpers (exact fp32 semantics, 2 MACs/instr) ----
__device__ __forceinline__ unsigned long long pack2(float lo, float hi) {
    unsigned long long r;
    asm("mov.b64 %0, {%1, %2};" : "=l"(r) : "f"(lo), "f"(hi));
    return r;
}
__device__ __forceinline__ unsigned long long dup2(float x) {
    unsigned long long r;
    asm("mov.b64 %0, {%1, %1};" : "=l"(r) : "f"(x));
    return r;
}
__device__ __forceinline__ void fma2(unsigned long long& acc, unsigned long long a, unsigned long long b) {
    asm("fma.rn.f32x2 %0, %1, %2, %0;" : "+l"(acc) : "l"(a), "l"(b));
}
__device__ __forceinline__ void unpack2(unsigned long long v, float& lo, float& hi) {
    asm("mov.b64 {%0, %1}, %2;" : "=f"(lo), "=f"(hi) : "l"(v));
}

__global__ void k_zero_stats()
{
    if (threadIdx.x < 64) g_stats[threadIdx.x] = 0.0f;
}

// Block = 256 threads = 64 nodes. Quad (4 lanes) per node:
// lane q loads row floats [4q,4q+4) via ONE LDG.128 (8 nodes/warp -> 8 lines
// -> 8 wavefronts per gather instruction: the LDG minimum for 64B rows).
// Exchange: shfl.xor(1) -> 8-ch group (predicated SELs, static indices),
// shfl.xor(2) -> other 8-ch group. Thread computes output channels [4q,4q+4)
// as 2 packed f32x2 accumulators; group offsets folded into SHARED weight ptrs.
template<int LAYER>
__global__ __launch_bounds__(256)
void k_conv(const float* __restrict__ src_param,  // LAYER1: data
            const int*   __restrict__ ind,
            const float* __restrict__ w,          // [c][o][j] : c*144 + o*9 + j
            const float* __restrict__ bias,       // LAYER1 only
            const float* __restrict__ gamma,      // LAYER2: gamma1
            const float* __restrict__ beta,      // LAYER2: beta1
            float*       __restrict__ dst_param,  // LAYER2: d_out
            int n, int stat_off_in, int stat_off_out)
{
    // device-side scratch selection (NEVER pass __device__ symbols from host)
    const float* src = (LAYER == 1) ? src_param : (const float*)g_y1;
    float*       dst = (LAYER == 1) ? (float*)g_y1 : dst_param;

    __shared__ __align__(16) float ws[2304];   // ws[j*256 + c*16 + o]
    __shared__ float s_ab[32];                 // a[16], b[16] (LAYER 2)
    __shared__ float s_stat[32];               // sum[16], ssq[16]

    const int tid = threadIdx.x;

    for (int s = tid; s < 2304; s += 256) {
        int o = s & 15, c = (s >> 4) & 15, j = s >> 8;
        ws[s] = w[c * 144 + o * 9 + j];
    }
    if (tid < 32) s_stat[tid] = 0.0f;
    if (LAYER == 2 && tid < 16) {
        float inv  = 1.0f / (float)n;
        float mean = g_stats[stat_off_in + tid] * inv;
        float var  = g_stats[stat_off_in + 16 + tid] * inv - mean * mean;
        float a    = gamma[tid] * rsqrtf(var + EPS);
        s_ab[tid]      = a;
        s_ab[16 + tid] = beta[tid] - a * mean;
    }
    __syncthreads();

    const int q    = tid & 3;                  // quarter: in/out channels [4q,4q+4)
    const int nl   = tid >> 2;                 // local node 0..63
    const int node = blockIdx.x * 64 + nl;
    const bool act = node < n;
    const int ibase = act ? node * 9 : 0;      // inactive lanes read valid ind[0..8]
    const int oq   = q * 4;

    const bool qodd  = (q & 1) != 0;
    const int aBase  = (q & 2) * 4;            // 0 or 8: my 8-channel group
    const int bBase  = 8 - aBase;              // the other group

    unsigned long long acc[2];
#pragma unroll
    for (int k = 0; k < 2; ++k)
        acc[k] = (LAYER == 1)
               ? pack2(__ldg(bias + oq + 2 * k), __ldg(bias + oq + 2 * k + 1))
               : pack2(0.0f, 0.0f);

    // weight views: runtime group/output offsets folded into SHARED pointers
    const float* w_a = ws + aBase * 16 + oq;   // channels aBase+k, outputs [oq,oq+4)
    const float* w_b = ws + bBase * 16 + oq;

    // software pipeline: prefetch row quarter for j+1 while computing j
    float4 cur;
    {
        int r0 = ind[ibase];
        cur = *reinterpret_cast<const float4*>(src + (size_t)r0 * 16 + oq);
    }

#pragma unroll 1   // compact body (I$ L0); cross-warp MLP hides L2 latency
    for (int j = 0; j < 9; ++j) {
        float4 nxt = make_float4(0.f, 0.f, 0.f, 0.f);
        if (j < 8) {
            int rn = ind[ibase + j + 1];
            nxt = *reinterpret_cast<const float4*>(src + (size_t)rn * 16 + oq);
        }

        float own[4] = {cur.x, cur.y, cur.z, cur.w};
        if (LAYER == 2) {
#pragma unroll
            for (int k = 0; k < 4; ++k) {
                float v = fmaf(own[k], s_ab[oq + k], s_ab[16 + oq + k]);
                own[k] = fmaxf(v, SLOPE * v);
            }
        }
        // round 1: xor 1 -> assemble my 8-channel group (static indices + SELs)
        float rcv[4];
#pragma unroll
        for (int k = 0; k < 4; ++k) rcv[k] = __shfl_xor_sync(0xFFFFFFFFu, own[k], 1);
        float a0 = qodd ? rcv[0] : own[0];
        float a1 = qodd ? rcv[1] : own[1];
        float a2 = qodd ? rcv[2] : own[2];
        float a3 = qodd ? rcv[3] : own[3];
        float a4 = qodd ? own[0] : rcv[0];
        float a5 = qodd ? own[1] : rcv[1];
        float a6 = qodd ? own[2] : rcv[2];
        float a7 = qodd ? own[3] : rcv[3];
        float av[8] = {a0, a1, a2, a3, a4, a5, a6, a7};
        // round 2: xor 2 -> the other 8-channel group, same ordering
        float bv[8];
#pragma unroll
        for (int k = 0; k < 8; ++k) bv[k] = __shfl_xor_sync(0xFFFFFFFFu, av[k], 2);

        const float* wja = w_a + j * 256;
        const float* wjb = w_b + j * 256;
#pragma unroll
        for (int k = 0; k < 8; ++k) {          // channels aBase+k
            unsigned long long xx = dup2(av[k]);
            ulonglong2 wp = *reinterpret_cast<const ulonglong2*>(wja + k * 16);
            fma2(acc[0], xx, wp.x);
            fma2(acc[1], xx, wp.y);
        }
#pragma unroll
        for (int k = 0; k < 8; ++k) {          // channels bBase+k
            unsigned long long xx = dup2(bv[k]);
            ulonglong2 wp = *reinterpret_cast<const ulonglong2*>(wjb + k * 16);
            fma2(acc[0], xx, wp.x);
            fma2(acc[1], xx, wp.y);
        }
        cur = nxt;
    }

    float ov[4];
    unpack2(acc[0], ov[0], ov[1]);
    unpack2(acc[1], ov[2], ov[3]);

    // ---- store: one STG.128 per thread; warp covers 8 consecutive nodes (512B contig) ----
    if (act) {
        *reinterpret_cast<float4*>(dst + (size_t)node * 16 + oq) =
            make_float4(ov[0], ov[1], ov[2], ov[3]);
    }

    // ---- fused stats: reduce over node lanes (xor 4,8,16 keep q in bits 0-1) ----
    float m = act ? 1.0f : 0.0f;
    float sv[4], qv[4];
#pragma unroll
    for (int k = 0; k < 4; ++k) { sv[k] = ov[k] * m; qv[k] = ov[k] * ov[k] * m; }
#pragma unroll
    for (int d = 4; d < 32; d <<= 1) {
#pragma unroll
        for (int k = 0; k < 4; ++k) {
            sv[k] += __shfl_xor_sync(0xFFFFFFFFu, sv[k], d);
            qv[k] += __shfl_xor_sync(0xFFFFFFFFu, qv[k], d);
        }
    }
    if ((tid & 31) < 4) {                      // lane L holds channels [4L,4L+4)
#pragma unroll
        for (int k = 0; k < 4; ++k) {
            atomicAdd(&s_stat[oq + k],      sv[k]);
            atomicAdd(&s_stat[16 + oq + k], qv[k]);
        }
    }
    __syncthreads();
    if (tid < 32) atomicAdd(&g_stats[stat_off_out + tid], s_stat[tid]);
}

// Final: out = leaky(a2[c]*y2 + b2[c] + data), in place on d_out.
__global__ __launch_bounds__(256)
void k_bnact2(const float* __restrict__ gamma,
              const float* __restrict__ beta,
              const float* __restrict__ res,
              float*       __restrict__ out,
              int n, int off)
{
    __shared__ float sa[16], sb[16];
    if (threadIdx.x < 16) {
        int c = threadIdx.x;
        float inv  = 1.0f / (float)n;
        float mean = g_stats[off + c] * inv;
        float var  = g_stats[off + 16 + c] * inv - mean * mean;
        float a    = gamma[c] * rsqrtf(var + EPS);
        sa[c] = a;
        sb[c] = beta[c] - a * mean;
    }
    __syncthreads();

    int n4 = n * 4;
    int stride = gridDim.x * 256;
    for (int i = blockIdx.x * 256 + threadIdx.x; i < n4; i += stride) {
        float4 v = reinterpret_cast<float4*>(out)[i];
        float4 r = reinterpret_cast<const float4*>(res)[i];
        int c0 = (i & 3) * 4;
        v.x = fmaf(v.x, sa[c0 + 0], sb[c0 + 0]) + r.x;  v.x = fmaxf(v.x, SLOPE * v.x);
        v.y = fmaf(v.y, sa[c0 + 1], sb[c0 + 1]) + r.y;  v.y = fmaxf(v.y, SLOPE * v.y);
        v.z = fmaf(v.z, sa[c0 + 2], sb[c0 + 2]) + r.z;  v.z = fmaxf(v.z, SLOPE * v.z);
        v.w = fmaf(v.w, sa[c0 + 3], sb[c0 + 3]) + r.w;  v.w = fmaxf(v.w, SLOPE * v.w);
        reinterpret_cast<float4*>(out)[i] = v;
    }
}

extern "C" void kernel_launch(void* const* d_in, const int* in_sizes, int n_in,
                              void* d_out, int out_size)
{
    const float* data   = (const float*)d_in[0];
    const int*   ind    = (const int*)  d_in[1];
    const float* w1     = (const float*)d_in[2];
    const float* b1     = (const float*)d_in[3];
    const float* gamma1 = (const float*)d_in[4];
    const float* beta1  = (const float*)d_in[5];
    const float* w2     = (const float*)d_in[6];
    const float* gamma2 = (const float*)d_in[7];
    const float* beta2  = (const float*)d_in[8];
    float*       out    = (float*)d_out;

    int n = in_sizes[0] / 16;
    if (n > NMAX) n = NMAX;

    int conv_blocks = (n + 63) / 64;
    int ew_blocks   = 1184;

    k_zero_stats<<<1, 64>>>();
    k_conv<1><<<conv_blocks, 256>>>(data, ind, w1, b1, nullptr, nullptr, nullptr, n, 0, 0);
    k_conv<2><<<conv_blocks, 256>>>(nullptr, ind, w2, nullptr, gamma1, beta1, out, n, 0, 32);
    k_bnact2<<<ew_blocks, 256>>>(gamma2, beta2, data, out, n, 32);
}

// round 14
// speedup vs baseline: 1.9719x; 1.9719x over previous
#include <cuda_runtime.h>
#include <cuda_bf16.h>

// ConvTreeBlock: N=1e6 nodes, C=16, KS=9.
// R10 = R7 (proven pair-gather + f32x2) with ONE change: each thread pair
// processes TWO nodes (A = base+nl, B = base+128+nl), so every weight LDS.128
// feeds FMAs of both nodes -> LDS wavefronts and issue per node-j ~halved.
// Fused stats + BN1-in-gather + device-side scratch selection kept.
// Launches: zero_stats -> conv1(+stats1) -> conv2(BN1+leaky inline, +stats2) -> bnact2.

#define NMAX 1000000

__device__ float g_y1[(size_t)NMAX * 16];   // conv1 raw output (device-side only!)
__device__ float g_stats[64];               // [0:16]sum1 [16:32]ssq1 [32:48]sum2 [48:64]ssq2

static constexpr float EPS   = 1e-5f;
static constexpr float SLOPE = 0.2f;

// ---- f32x2 helpers (exact fp32 semantics, 2 MACs/instr) ----
__device__ __forceinline__ unsigned long long pack2(float lo, float hi) {
    unsigned long long r;
    asm("mov.b64 %0, {%1, %2};" : "=l"(r) : "f"(lo), "f"(hi));
    return r;
}
__device__ __forceinline__ unsigned long long dup2(float x) {
    unsigned long long r;
    asm("mov.b64 %0, {%1, %1};" : "=l"(r) : "f"(x));
    return r;
}
__device__ __forceinline__ void fma2(unsigned long long& acc, unsigned long long a, unsigned long long b) {
    asm("fma.rn.f32x2 %0, %1, %2, %0;" : "+l"(acc) : "l"(a), "l"(b));
}
__device__ __forceinline__ void unpack2(unsigned long long v, float& lo, float& hi) {
    asm("mov.b64 {%0, %1}, %2;" : "=f"(lo), "=f"(hi) : "l"(v));
}

__global__ void k_zero_stats()
{
    if (threadIdx.x < 64) g_stats[threadIdx.x] = 0.0f;
}

// Block = 256 threads = 256 nodes (2 per thread pair).
// Thread pair (2*nl, 2*nl+1): thread p loads row-half [8p,8p+8) for BOTH its
// nodes (4x LDG.128/j, pair shares 128B lines), exchanges halves via
// shfl.xor(1), computes output channels [8p,8p+8) for both nodes as
// 2x4 packed f32x2 accumulators. One weight LDS.128 serves both nodes.
template<int LAYER>
__global__ __launch_bounds__(256)
void k_conv(const float* __restrict__ src_param,  // LAYER1: data
            const int*   __restrict__ ind,
            const float* __restrict__ w,          // [c][o][j] : c*144 + o*9 + j
            const float* __restrict__ bias,       // LAYER1 only
            const float* __restrict__ gamma,      // LAYER2: gamma1
            const float* __restrict__ beta,       // LAYER2: beta1
            float*       __restrict__ dst_param,  // LAYER2: d_out
            int n, int stat_off_in, int stat_off_out)
{
    // device-side scratch selection (NEVER pass __device__ symbols from host)
    const float* src = (LAYER == 1) ? src_param : (const float*)g_y1;
    float*       dst = (LAYER == 1) ? (float*)g_y1 : dst_param;

    __shared__ __align__(16) float ws[2304];   // ws[j*256 + c*16 + o]
    __shared__ float s_ab[32];                 // a[16], b[16] (LAYER 2)
    __shared__ float s_stat[32];               // sum[16], ssq[16]

    const int tid = threadIdx.x;

    for (int s = tid; s < 2304; s += 256) {
        int o = s & 15, c = (s >> 4) & 15, j = s >> 8;
        ws[s] = w[c * 144 + o * 9 + j];
    }
    if (tid < 32) s_stat[tid] = 0.0f;
    if (LAYER == 2 && tid < 16) {
        float inv  = 1.0f / (float)n;
        float mean = g_stats[stat_off_in + tid] * inv;
        float var  = g_stats[stat_off_in + 16 + tid] * inv - mean * mean;
        float a    = gamma[tid] * rsqrtf(var + EPS);
        s_ab[tid]      = a;
        s_ab[16 + tid] = beta[tid] - a * mean;
    }
    __syncthreads();

    const int nl    = tid >> 1;                // pair index 0..127
    const int p     = tid & 1;                 // half: channels [8p, 8p+8)
    const int nodeA = blockIdx.x * 256 + nl;
    const int nodeB = nodeA + 128;
    const bool actA = nodeA < n;
    const bool actB = nodeB < n;
    const int ibaseA = actA ? nodeA * 9 : 0;
    const int ibaseB = actB ? nodeB * 9 : 0;

    unsigned long long accA[4], accB[4];
#pragma unroll
    for (int k = 0; k < 4; ++k) {
        unsigned long long b0 = (LAYER == 1)
            ? pack2(__ldg(bias + p * 8 + 2 * k), __ldg(bias + p * 8 + 2 * k + 1))
            : pack2(0.0f, 0.0f);
        accA[k] = b0;
        accB[k] = b0;
    }

    // per-thread weight views (runtime p offset into SHARED mem; p=0/1 bases
    // 136 floats apart -> different banks, conflict-free broadcast pair)
    const float* w_own = ws + (p * 8) * 16 + p * 8;        // own-half input channels
    const float* w_oth = ws + ((1 - p) * 8) * 16 + p * 8;  // partner-half input channels

    // software pipeline: prefetch both nodes' row-halves for j+1 while computing j
    float4 cA0, cA1, cB0, cB1;
    {
        int rA = ind[ibaseA];
        int rB = ind[ibaseB];
        const float* rpA = src + (size_t)rA * 16 + p * 8;
        const float* rpB = src + (size_t)rB * 16 + p * 8;
        cA0 = *reinterpret_cast<const float4*>(rpA);
        cA1 = *reinterpret_cast<const float4*>(rpA + 4);
        cB0 = *reinterpret_cast<const float4*>(rpB);
        cB1 = *reinterpret_cast<const float4*>(rpB + 4);
    }

#pragma unroll 1   // ~4KB body, fits I$ L0; cross-warp MLP hides L2 latency
    for (int j = 0; j < 9; ++j) {
        float4 nA0 = make_float4(0.f, 0.f, 0.f, 0.f), nA1 = nA0, nB0 = nA0, nB1 = nA0;
        if (j < 8) {
            int rA = ind[ibaseA + j + 1];
            int rB = ind[ibaseB + j + 1];
            const float* rpA = src + (size_t)rA * 16 + p * 8;
            const float* rpB = src + (size_t)rB * 16 + p * 8;
            nA0 = *reinterpret_cast<const float4*>(rpA);
            nA1 = *reinterpret_cast<const float4*>(rpA + 4);
            nB0 = *reinterpret_cast<const float4*>(rpB);
            nB1 = *reinterpret_cast<const float4*>(rpB + 4);
        }

        float ownA[8] = {cA0.x, cA0.y, cA0.z, cA0.w, cA1.x, cA1.y, cA1.z, cA1.w};
        float ownB[8] = {cB0.x, cB0.y, cB0.z, cB0.w, cB1.x, cB1.y, cB1.z, cB1.w};
        if (LAYER == 2) {
#pragma unroll
            for (int k = 0; k < 8; ++k) {
                float a = s_ab[p * 8 + k], b = s_ab[16 + p * 8 + k];
                float vA = fmaf(ownA[k], a, b);
                float vB = fmaf(ownB[k], a, b);
                ownA[k] = fmaxf(vA, SLOPE * vA);
                ownB[k] = fmaxf(vB, SLOPE * vB);
            }
        }
        float othA[8], othB[8];
#pragma unroll
        for (int k = 0; k < 8; ++k) {
            othA[k] = __shfl_xor_sync(0xFFFFFFFFu, ownA[k], 1);
            othB[k] = __shfl_xor_sync(0xFFFFFFFFu, ownB[k], 1);
        }

        const float* wj_own = w_own + j * 256;
        const float* wj_oth = w_oth + j * 256;
#pragma unroll
        for (int k = 0; k < 8; ++k) {          // input channel p*8+k (both nodes)
            unsigned long long xA = dup2(ownA[k]);
            unsigned long long xB = dup2(ownB[k]);
            ulonglong2 w01 = *reinterpret_cast<const ulonglong2*>(wj_own + k * 16);
            ulonglong2 w23 = *reinterpret_cast<const ulonglong2*>(wj_own + k * 16 + 4);
            fma2(accA[0], xA, w01.x);  fma2(accB[0], xB, w01.x);
            fma2(accA[1], xA, w01.y);  fma2(accB[1], xB, w01.y);
            fma2(accA[2], xA, w23.x);  fma2(accB[2], xB, w23.x);
            fma2(accA[3], xA, w23.y);  fma2(accB[3], xB, w23.y);
        }
#pragma unroll
        for (int k = 0; k < 8; ++k) {          // input channel (1-p)*8+k (both nodes)
            unsigned long long xA = dup2(othA[k]);
            unsigned long long xB = dup2(othB[k]);
            ulonglong2 w01 = *reinterpret_cast<const ulonglong2*>(wj_oth + k * 16);
            ulonglong2 w23 = *reinterpret_cast<const ulonglong2*>(wj_oth + k * 16 + 4);
            fma2(accA[0], xA, w01.x);  fma2(accB[0], xB, w01.x);
            fma2(accA[1], xA, w01.y);  fma2(accB[1], xB, w01.y);
            fma2(accA[2], xA, w23.x);  fma2(accB[2], xB, w23.x);
            fma2(accA[3], xA, w23.y);  fma2(accB[3], xB, w23.y);
        }
        cA0 = nA0; cA1 = nA1; cB0 = nB0; cB1 = nB1;
    }

    float avA[8], avB[8];
#pragma unroll
    for (int k = 0; k < 4; ++k) {
        unpack2(accA[k], avA[2 * k], avA[2 * k + 1]);
        unpack2(accB[k], avB[2 * k], avB[2 * k + 1]);
    }

    // ---- stores (coalesced STG.128 x2 per node) ----
    if (actA) {
        float4* o4 = reinterpret_cast<float4*>(dst + (size_t)nodeA * 16 + p * 8);
        o4[0] = make_float4(avA[0], avA[1], avA[2], avA[3]);
        o4[1] = make_float4(avA[4], avA[5], avA[6], avA[7]);
    }
    if (actB) {
        float4* o4 = reinterpret_cast<float4*>(dst + (size_t)nodeB * 16 + p * 8);
        o4[0] = make_float4(avB[0], avB[1], avB[2], avB[3]);
        o4[1] = make_float4(avB[4], avB[5], avB[6], avB[7]);
    }

    // ---- fused stats: both nodes folded in; reduce over node lanes ----
    float mA = actA ? 1.0f : 0.0f;
    float mB = actB ? 1.0f : 0.0f;
    float sv[8], qv[8];
#pragma unroll
    for (int k = 0; k < 8; ++k) {
        sv[k] = avA[k] * mA + avB[k] * mB;
        qv[k] = avA[k] * avA[k] * mA + avB[k] * avB[k] * mB;
    }
#pragma unroll
    for (int d = 2; d < 32; d <<= 1) {
#pragma unroll
        for (int k = 0; k < 8; ++k) {
            sv[k] += __shfl_xor_sync(0xFFFFFFFFu, sv[k], d);
            qv[k] += __shfl_xor_sync(0xFFFFFFFFu, qv[k], d);
        }
    }
    if ((tid & 31) < 2) {    // lane0: p=0 (ch0..7), lane1: p=1 (ch8..15)
#pragma unroll
        for (int k = 0; k < 8; ++k) {
            atomicAdd(&s_stat[p * 8 + k],      sv[k]);
            atomicAdd(&s_stat[16 + p * 8 + k], qv[k]);
        }
    }
    __syncthreads();
    if (tid < 32) atomicAdd(&g_stats[stat_off_out + tid], s_stat[tid]);
}

// Final: out = leaky(a2[c]*y2 + b2[c] + data), in place on d_out.
__global__ __launch_bounds__(256)
void k_bnact2(const float* __restrict__ gamma,
              const float* __restrict__ beta,
              const float* __restrict__ res,
              float*       __restrict__ out,
              int n, int off)
{
    __shared__ float sa[16], sb[16];
    if (threadIdx.x < 16) {
        int c = threadIdx.x;
        float inv  = 1.0f / (float)n;
        float mean = g_stats[off + c] * inv;
        float var  = g_stats[off + 16 + c] * inv - mean * mean;
        float a    = gamma[c] * rsqrtf(var + EPS);
        sa[c] = a;
        sb[c] = beta[c] - a * mean;
    }
    __syncthreads();

    int n4 = n * 4;
    int stride = gridDim.x * 256;
    for (int i = blockIdx.x * 256 + threadIdx.x; i < n4; i += stride) {
        float4 v = reinterpret_cast<float4*>(out)[i];
        float4 r = reinterpret_cast<const float4*>(res)[i];
        int c0 = (i & 3) * 4;
        v.x = fmaf(v.x, sa[c0 + 0], sb[c0 + 0]) + r.x;  v.x = fmaxf(v.x, SLOPE * v.x);
        v.y = fmaf(v.y, sa[c0 + 1], sb[c0 + 1]) + r.y;  v.y = fmaxf(v.y, SLOPE * v.y);
        v.z = fmaf(v.z, sa[c0 + 2], sb[c0 + 2]) + r.z;  v.z = fmaxf(v.z, SLOPE * v.z);
        v.w = fmaf(v.w, sa[c0 + 3], sb[c0 + 3]) + r.w;  v.w = fmaxf(v.w, SLOPE * v.w);
        reinterpret_cast<float4*>(out)[i] = v;
    }
}

extern "C" void kernel_launch(void* const* d_in, const int* in_sizes, int n_in,
                              void* d_out, int out_size)
{
    const float* data   = (const float*)d_in[0];
    const int*   ind    = (const int*)  d_in[1];
    const float* w1     = (const float*)d_in[2];
    const float* b1     = (const float*)d_in[3];
    const float* gamma1 = (const float*)d_in[4];
    const float* beta1  = (const float*)d_in[5];
    const float* w2     = (const float*)d_in[6];
    const float* gamma2 = (const float*)d_in[7];
    const float* beta2  = (const float*)d_in[8];
    float*       out    = (float*)d_out;

    int n = in_sizes[0] / 16;
    if (n > NMAX) n = NMAX;

    int conv_blocks = (n + 255) / 256;   // 256 nodes per block (2 per pair)
    int ew_blocks   = 1184;

    k_zero_stats<<<1, 64>>>();
    k_conv<1><<<conv_blocks, 256>>>(data, ind, w1, b1, nullptr, nullptr, nullptr, n, 0, 0);
    k_conv<2><<<conv_blocks, 256>>>(nullptr, ind, w2, nullptr, gamma1, beta1, out, n, 0, 32);
    k_bnact2<<<ew_blocks, 256>>>(gamma2, beta2, data, out, n, 32);
}